// round 13
// baseline (speedup 1.0000x reference)
#include <cuda_runtime.h>

// Problem constants (fixed shapes from reference setup_inputs)
#define B_    4
#define N_    16384
#define C2D   128
#define C3D   128
#define Him   96
#define Wim   160
#define HW    15360          // Him*Wim
#define CO    128            // output channels
#define CI    256            // C2D + C3D
#define TN    64             // points per CTA tile
#define SB_STRIDE 260        // s_b row stride in floats (4*65: float4-aligned, odd/4 for banking)

typedef unsigned long long ull;

// Scratch (allocation-free rule: __device__ globals)
__device__ float g_f2dt[B_ * HW * C2D];   // feat_2d transposed to [b][p][c]
__device__ float g_WT[CI * CO];           // W transposed to [k][m]

__device__ __forceinline__ ull fma2(ull a, ull b, ull c) {
    ull d;
    asm("fma.rn.f32x2 %0, %1, %2, %3;" : "=l"(d) : "l"(a), "l"(b), "l"(c));
    return d;
}
__device__ __forceinline__ ull pack2(float lo, float hi) {
    ull d;
    asm("mov.b64 %0, {%1, %2};" : "=l"(d) : "f"(lo), "f"(hi));
    return d;
}
__device__ __forceinline__ void unpack2(ull v, float& lo, float& hi) {
    asm("mov.b64 {%0, %1}, %2;" : "=f"(lo), "=f"(hi) : "l"(v));
}

// ---------------------------------------------------------------------------
// Kernel 1: transpose feat_2d [B, C, H*W] -> g_f2dt [B, H*W, C]
// so the bilinear gather becomes contiguous 512B per corner.
// ---------------------------------------------------------------------------
__global__ void k_transpose_f2d(const float* __restrict__ f2d) {
    __shared__ float t[32][33];
    const int b  = blockIdx.z;
    const int c0 = blockIdx.y * 32;
    const int p0 = blockIdx.x * 32;
    const int tx = threadIdx.x, ty = threadIdx.y;   // 32 x 8

    const float* src = f2d + ((size_t)(b * C2D + c0)) * HW + p0;
#pragma unroll
    for (int r = 0; r < 32; r += 8)
        t[ty + r][tx] = src[(size_t)(ty + r) * HW + tx];
    __syncthreads();

    float* dst = g_f2dt + ((size_t)(b * HW + p0)) * C2D + c0;
#pragma unroll
    for (int r = 0; r < 32; r += 8)
        dst[(size_t)(ty + r) * C2D + tx] = t[tx][ty + r];
}

// ---------------------------------------------------------------------------
// Kernel 2: transpose W [M=128, K=256] -> g_WT [K][M]  (tiny, 128 KB)
// ---------------------------------------------------------------------------
__global__ void k_transpose_w(const float* __restrict__ Wm) {
    int idx = blockIdx.x * 256 + threadIdx.x;   // idx = k*128 + m
    int k = idx >> 7, m = idx & 127;
    g_WT[idx] = Wm[m * CI + k];
}

// ---------------------------------------------------------------------------
// Kernel 3: fused bilinear sample + concat + GEMM + bias + leaky ReLU.
// Per CTA: batch b, 64-point tile. 256 threads.
//   smem s_b[64][260]: cat tile, n-major (k-contiguous rows)
//   smem s_w[64][128]: W chunk, k-major (m-contiguous rows)
// Thread tile: 8 M (4 f32x2 pairs) x 4 N.  n_j = n0 + tx + 16*j, m = ty*8+u.
// ---------------------------------------------------------------------------
__global__ __launch_bounds__(256, 2)
void k_fused(const float* __restrict__ xy, const float* __restrict__ f3d,
             const float* __restrict__ bias, float* __restrict__ out) {
    extern __shared__ float smem[];
    float* s_b = smem;                       // 64*260 floats = 66560 B
    float* s_w = smem + TN * SB_STRIDE;      // 64*128 floats = 32768 B

    const int tile = blockIdx.x;
    const int b    = blockIdx.y;
    const int tid  = threadIdx.x;
    const int tx   = tid & 15;
    const int ty   = tid >> 4;
    const int lane = tid & 31;
    const int warp = tid >> 5;
    const int n0   = tile * TN;

    // ---- Phase 1: bilinear sampling into s_b[n][0..127]. 8 points per warp;
    //      lane handles channels 4*lane..4*lane+3 (contiguous -> coalesced).
    {
        const float* xb = xy + (size_t)b * 2 * N_;
        const float* f2 = g_f2dt + (size_t)b * HW * C2D;
#pragma unroll
        for (int i = 0; i < TN / 8; i++) {
            const int n  = warp * (TN / 8) + i;
            const int gn = n0 + n;
            const float x = xb[gn];
            const float y = xb[N_ + gn];
            const float xf = floorf(x), yf = floorf(y);
            const int ix0 = (int)xf, iy0 = (int)yf;
            const int ix1 = ix0 + 1, iy1 = iy0 + 1;
            const float wx1 = x - xf, wy1 = y - yf;
            const float wx0 = 1.f - wx1, wy0 = 1.f - wy1;
            float w00 = wx0 * wy0, w10 = wx1 * wy0;
            float w01 = wx0 * wy1, w11 = wx1 * wy1;
            const bool vx0 = (ix0 >= 0) & (ix0 < Wim);
            const bool vx1 = (ix1 >= 0) & (ix1 < Wim);
            const bool vy0 = (iy0 >= 0) & (iy0 < Him);
            const bool vy1 = (iy1 >= 0) & (iy1 < Him);
            if (!(vx0 & vy0)) w00 = 0.f;
            if (!(vx1 & vy0)) w10 = 0.f;
            if (!(vx0 & vy1)) w01 = 0.f;
            if (!(vx1 & vy1)) w11 = 0.f;
            const int cx0 = min(max(ix0, 0), Wim - 1);
            const int cx1 = min(max(ix1, 0), Wim - 1);
            const int cy0 = min(max(iy0, 0), Him - 1);
            const int cy1 = min(max(iy1, 0), Him - 1);
            const float4 v00 = *reinterpret_cast<const float4*>(f2 + (size_t)(cy0 * Wim + cx0) * C2D + 4 * lane);
            const float4 v10 = *reinterpret_cast<const float4*>(f2 + (size_t)(cy0 * Wim + cx1) * C2D + 4 * lane);
            const float4 v01 = *reinterpret_cast<const float4*>(f2 + (size_t)(cy1 * Wim + cx0) * C2D + 4 * lane);
            const float4 v11 = *reinterpret_cast<const float4*>(f2 + (size_t)(cy1 * Wim + cx1) * C2D + 4 * lane);
            float4 acc;
            acc.x = w00 * v00.x + w10 * v10.x + w01 * v01.x + w11 * v11.x;
            acc.y = w00 * v00.y + w10 * v10.y + w01 * v01.y + w11 * v11.y;
            acc.z = w00 * v00.z + w10 * v10.z + w01 * v01.z + w11 * v11.z;
            acc.w = w00 * v00.w + w10 * v10.w + w01 * v01.w + w11 * v11.w;
            *reinterpret_cast<float4*>(s_b + n * SB_STRIDE + 4 * lane) = acc;
        }
    }

    // ---- Phase 2: feat_3d tile into s_b[n][128..255] (coalesced reads,
    //      4-way-conflict scalar smem transpose stores — cheap vs GEMM).
    {
        const float* f3 = f3d + (size_t)b * C3D * N_;
        const int c_off = tid >> 6;      // 0..3
        const int nn    = tid & 63;
#pragma unroll 4
        for (int it = 0; it < 32; it++) {
            const int c = it * 4 + c_off;
            s_b[nn * SB_STRIDE + C2D + c] = f3[(size_t)c * N_ + n0 + nn];
        }
    }

    // ---- Phase 3: GEMM, K streamed in 4 chunks of 64 via s_w; FMA2 inner loop.
    ull acc2[4][4];
#pragma unroll
    for (int u = 0; u < 4; u++)
#pragma unroll
        for (int j = 0; j < 4; j++) acc2[u][j] = 0ull;

    for (int kc = 0; kc < 4; kc++) {
        if (kc) __syncthreads();   // previous chunk consumed
        // load W chunk: rows k = kc*64..+63, each 128 floats; one row per warp
#pragma unroll
        for (int it = 0; it < 8; it++) {
            const int r = it * 8 + warp;
            *reinterpret_cast<float4*>(s_w + r * CO + 4 * lane) =
                *reinterpret_cast<const float4*>(g_WT + (size_t)(kc * 64 + r) * CO + 4 * lane);
        }
        __syncthreads();           // also orders s_b fill before first compute

        const float* bbase = s_b + kc * 64;
#pragma unroll 4
        for (int kq = 0; kq < 16; kq++) {
            float bvf[4][4];
#pragma unroll
            for (int j = 0; j < 4; j++) {
                const float4 t4 = *reinterpret_cast<const float4*>(
                    bbase + (tx + 16 * j) * SB_STRIDE + kq * 4);
                bvf[j][0] = t4.x; bvf[j][1] = t4.y; bvf[j][2] = t4.z; bvf[j][3] = t4.w;
            }
#pragma unroll
            for (int ks = 0; ks < 4; ks++) {
                const float* wr = s_w + (kq * 4 + ks) * CO + ty * 8;
                const ull a0 = *reinterpret_cast<const ull*>(wr + 0);
                const ull a1 = *reinterpret_cast<const ull*>(wr + 2);
                const ull a2 = *reinterpret_cast<const ull*>(wr + 4);
                const ull a3 = *reinterpret_cast<const ull*>(wr + 6);
#pragma unroll
                for (int j = 0; j < 4; j++) {
                    const ull bb = pack2(bvf[j][ks], bvf[j][ks]);
                    acc2[0][j] = fma2(a0, bb, acc2[0][j]);
                    acc2[1][j] = fma2(a1, bb, acc2[1][j]);
                    acc2[2][j] = fma2(a2, bb, acc2[2][j]);
                    acc2[3][j] = fma2(a3, bb, acc2[3][j]);
                }
            }
        }
    }

    // ---- Epilogue: bias + leaky ReLU + store
    const int m0 = ty * 8;
    float bi[8];
#pragma unroll
    for (int u = 0; u < 8; u++) bi[u] = bias[m0 + u];
    float* ob = out + (size_t)b * CO * N_ + n0;
#pragma unroll
    for (int u = 0; u < 4; u++) {
#pragma unroll
        for (int j = 0; j < 4; j++) {
            float lo, hi;
            unpack2(acc2[u][j], lo, hi);
            lo += bi[2 * u];
            hi += bi[2 * u + 1];
            lo = (lo >= 0.f) ? lo : 0.1f * lo;
            hi = (hi >= 0.f) ? hi : 0.1f * hi;
            const int n = tx + 16 * j;
            ob[(size_t)(m0 + 2 * u) * N_ + n]     = lo;
            ob[(size_t)(m0 + 2 * u + 1) * N_ + n] = hi;
        }
    }
}

// ---------------------------------------------------------------------------
// Inputs (metadata order): 0 xy [4,2,16384] f32, 1 feat_2d [4,128,96,160] f32,
// 2 feat_3d [4,128,16384] f32, 3 W [128,256] f32, 4 b [128] f32.
// Output: [4,128,16384] f32.
// ---------------------------------------------------------------------------
extern "C" void kernel_launch(void* const* d_in, const int* in_sizes, int n_in,
                              void* d_out, int out_size) {
    const float* xy   = (const float*)d_in[0];
    const float* f2d  = (const float*)d_in[1];
    const float* f3d  = (const float*)d_in[2];
    const float* Wm   = (const float*)d_in[3];
    const float* bias = (const float*)d_in[4];
    float* out = (float*)d_out;

    k_transpose_f2d<<<dim3(HW / 32, C2D / 32, B_), dim3(32, 8)>>>(f2d);
    k_transpose_w<<<(CI * CO) / 256, 256>>>(Wm);

    const int smem_bytes = (TN * SB_STRIDE + 64 * CO) * (int)sizeof(float); // 99328
    cudaFuncSetAttribute(k_fused, cudaFuncAttributeMaxDynamicSharedMemorySize, smem_bytes);
    k_fused<<<dim3(N_ / TN, B_), 256, smem_bytes>>>(xy, f3d, bias, out);
}

// round 14
// speedup vs baseline: 1.0122x; 1.0122x over previous
#include <cuda_runtime.h>

// Problem constants (fixed shapes from reference setup_inputs)
#define B_    4
#define N_    16384
#define C2D   128
#define C3D   128
#define Him   96
#define Wim   160
#define HW    15360          // Him*Wim
#define CO    128            // output channels
#define CI    256            // C2D + C3D
#define TN    64             // points per CTA tile
#define SB_STRIDE 260        // s_b row stride in floats (4*65: float4-aligned, odd/4 for banking)

typedef unsigned long long ull;

// Scratch (allocation-free rule: __device__ globals)
__device__ float g_f2dt[B_ * HW * C2D];   // feat_2d transposed to [b][p][c]
__device__ float g_WT[CI * CO];           // W transposed to [k][m]

__device__ __forceinline__ ull fma2(ull a, ull b, ull c) {
    ull d;
    asm("fma.rn.f32x2 %0, %1, %2, %3;" : "=l"(d) : "l"(a), "l"(b), "l"(c));
    return d;
}
__device__ __forceinline__ ull pack2(float lo, float hi) {
    ull d;
    asm("mov.b64 %0, {%1, %2};" : "=l"(d) : "f"(lo), "f"(hi));
    return d;
}
__device__ __forceinline__ void unpack2(ull v, float& lo, float& hi) {
    asm("mov.b64 {%0, %1}, %2;" : "=f"(lo), "=f"(hi) : "l"(v));
}

// ---------------------------------------------------------------------------
// Kernel 1: transpose feat_2d [B, C, H*W] -> g_f2dt [B, H*W, C]
// so the bilinear gather becomes contiguous 512B per corner.
// ---------------------------------------------------------------------------
__global__ void k_transpose_f2d(const float* __restrict__ f2d) {
    __shared__ float t[32][33];
    const int b  = blockIdx.z;
    const int c0 = blockIdx.y * 32;
    const int p0 = blockIdx.x * 32;
    const int tx = threadIdx.x, ty = threadIdx.y;   // 32 x 8

    const float* src = f2d + ((size_t)(b * C2D + c0)) * HW + p0;
#pragma unroll
    for (int r = 0; r < 32; r += 8)
        t[ty + r][tx] = src[(size_t)(ty + r) * HW + tx];
    __syncthreads();

    float* dst = g_f2dt + ((size_t)(b * HW + p0)) * C2D + c0;
#pragma unroll
    for (int r = 0; r < 32; r += 8)
        dst[(size_t)(ty + r) * C2D + tx] = t[tx][ty + r];
}

// ---------------------------------------------------------------------------
// Kernel 2: transpose W [M=128, K=256] -> g_WT [K][M]  (tiny, 128 KB)
// ---------------------------------------------------------------------------
__global__ void k_transpose_w(const float* __restrict__ Wm) {
    int idx = blockIdx.x * 256 + threadIdx.x;   // idx = k*128 + m
    int k = idx >> 7, m = idx & 127;
    g_WT[idx] = Wm[m * CI + k];
}

// ---------------------------------------------------------------------------
// Kernel 3: fused bilinear sample + concat + GEMM + bias + leaky ReLU.
// Per CTA: batch b, 64-point tile. 256 threads.
//   smem s_b[64][260]: cat tile, n-major (k-contiguous rows)
//   smem s_w[64][128]: W chunk, k-major (m-contiguous rows)
// Thread tile: 8 M (4 f32x2 pairs) x 4 N.  n_j = n0 + tx + 16*j, m = ty*8+u.
// ---------------------------------------------------------------------------
__global__ __launch_bounds__(256, 2)
void k_fused(const float* __restrict__ xy, const float* __restrict__ f3d,
             const float* __restrict__ bias, float* __restrict__ out) {
    extern __shared__ float smem[];
    float* s_b = smem;                       // 64*260 floats = 66560 B
    float* s_w = smem + TN * SB_STRIDE;      // 64*128 floats = 32768 B

    const int tile = blockIdx.x;
    const int b    = blockIdx.y;
    const int tid  = threadIdx.x;
    const int tx   = tid & 15;
    const int ty   = tid >> 4;
    const int lane = tid & 31;
    const int warp = tid >> 5;
    const int n0   = tile * TN;

    // ---- Phase 1: bilinear sampling into s_b[n][0..127]. 8 points per warp;
    //      lane handles channels 4*lane..4*lane+3 (contiguous -> coalesced).
    {
        const float* xb = xy + (size_t)b * 2 * N_;
        const float* f2 = g_f2dt + (size_t)b * HW * C2D;
#pragma unroll
        for (int i = 0; i < TN / 8; i++) {
            const int n  = warp * (TN / 8) + i;
            const int gn = n0 + n;
            const float x = xb[gn];
            const float y = xb[N_ + gn];
            const float xf = floorf(x), yf = floorf(y);
            const int ix0 = (int)xf, iy0 = (int)yf;
            const int ix1 = ix0 + 1, iy1 = iy0 + 1;
            const float wx1 = x - xf, wy1 = y - yf;
            const float wx0 = 1.f - wx1, wy0 = 1.f - wy1;
            float w00 = wx0 * wy0, w10 = wx1 * wy0;
            float w01 = wx0 * wy1, w11 = wx1 * wy1;
            const bool vx0 = (ix0 >= 0) & (ix0 < Wim);
            const bool vx1 = (ix1 >= 0) & (ix1 < Wim);
            const bool vy0 = (iy0 >= 0) & (iy0 < Him);
            const bool vy1 = (iy1 >= 0) & (iy1 < Him);
            if (!(vx0 & vy0)) w00 = 0.f;
            if (!(vx1 & vy0)) w10 = 0.f;
            if (!(vx0 & vy1)) w01 = 0.f;
            if (!(vx1 & vy1)) w11 = 0.f;
            const int cx0 = min(max(ix0, 0), Wim - 1);
            const int cx1 = min(max(ix1, 0), Wim - 1);
            const int cy0 = min(max(iy0, 0), Him - 1);
            const int cy1 = min(max(iy1, 0), Him - 1);
            const float4 v00 = *reinterpret_cast<const float4*>(f2 + (size_t)(cy0 * Wim + cx0) * C2D + 4 * lane);
            const float4 v10 = *reinterpret_cast<const float4*>(f2 + (size_t)(cy0 * Wim + cx1) * C2D + 4 * lane);
            const float4 v01 = *reinterpret_cast<const float4*>(f2 + (size_t)(cy1 * Wim + cx0) * C2D + 4 * lane);
            const float4 v11 = *reinterpret_cast<const float4*>(f2 + (size_t)(cy1 * Wim + cx1) * C2D + 4 * lane);
            float4 acc;
            acc.x = w00 * v00.x + w10 * v10.x + w01 * v01.x + w11 * v11.x;
            acc.y = w00 * v00.y + w10 * v10.y + w01 * v01.y + w11 * v11.y;
            acc.z = w00 * v00.z + w10 * v10.z + w01 * v01.z + w11 * v11.z;
            acc.w = w00 * v00.w + w10 * v10.w + w01 * v01.w + w11 * v11.w;
            *reinterpret_cast<float4*>(s_b + n * SB_STRIDE + 4 * lane) = acc;
        }
    }

    // ---- Phase 2: feat_3d tile into s_b[n][128..255] (coalesced reads,
    //      4-way-conflict scalar smem transpose stores — cheap vs GEMM).
    {
        const float* f3 = f3d + (size_t)b * C3D * N_;
        const int c_off = tid >> 6;      // 0..3
        const int nn    = tid & 63;
#pragma unroll 4
        for (int it = 0; it < 32; it++) {
            const int c = it * 4 + c_off;
            s_b[nn * SB_STRIDE + C2D + c] = f3[(size_t)c * N_ + n0 + nn];
        }
    }

    // ---- Phase 3: GEMM, K streamed in 4 chunks of 64 via s_w; FMA2 inner loop.
    ull acc2[4][4];
#pragma unroll
    for (int u = 0; u < 4; u++)
#pragma unroll
        for (int j = 0; j < 4; j++) acc2[u][j] = 0ull;

    for (int kc = 0; kc < 4; kc++) {
        if (kc) __syncthreads();   // previous chunk consumed
        // load W chunk: rows k = kc*64..+63, each 128 floats; one row per warp
#pragma unroll
        for (int it = 0; it < 8; it++) {
            const int r = it * 8 + warp;
            *reinterpret_cast<float4*>(s_w + r * CO + 4 * lane) =
                *reinterpret_cast<const float4*>(g_WT + (size_t)(kc * 64 + r) * CO + 4 * lane);
        }
        __syncthreads();           // also orders s_b fill before first compute

        const float* bbase = s_b + kc * 64;
#pragma unroll 4
        for (int kq = 0; kq < 16; kq++) {
            float bvf[4][4];
#pragma unroll
            for (int j = 0; j < 4; j++) {
                const float4 t4 = *reinterpret_cast<const float4*>(
                    bbase + (tx + 16 * j) * SB_STRIDE + kq * 4);
                bvf[j][0] = t4.x; bvf[j][1] = t4.y; bvf[j][2] = t4.z; bvf[j][3] = t4.w;
            }
#pragma unroll
            for (int ks = 0; ks < 4; ks++) {
                const float* wr = s_w + (kq * 4 + ks) * CO + ty * 8;
                const ull a0 = *reinterpret_cast<const ull*>(wr + 0);
                const ull a1 = *reinterpret_cast<const ull*>(wr + 2);
                const ull a2 = *reinterpret_cast<const ull*>(wr + 4);
                const ull a3 = *reinterpret_cast<const ull*>(wr + 6);
#pragma unroll
                for (int j = 0; j < 4; j++) {
                    const ull bb = pack2(bvf[j][ks], bvf[j][ks]);
                    acc2[0][j] = fma2(a0, bb, acc2[0][j]);
                    acc2[1][j] = fma2(a1, bb, acc2[1][j]);
                    acc2[2][j] = fma2(a2, bb, acc2[2][j]);
                    acc2[3][j] = fma2(a3, bb, acc2[3][j]);
                }
            }
        }
    }

    // ---- Epilogue: bias + leaky ReLU + store
    const int m0 = ty * 8;
    float bi[8];
#pragma unroll
    for (int u = 0; u < 8; u++) bi[u] = bias[m0 + u];
    float* ob = out + (size_t)b * CO * N_ + n0;
#pragma unroll
    for (int u = 0; u < 4; u++) {
#pragma unroll
        for (int j = 0; j < 4; j++) {
            float lo, hi;
            unpack2(acc2[u][j], lo, hi);
            lo += bi[2 * u];
            hi += bi[2 * u + 1];
            lo = (lo >= 0.f) ? lo : 0.1f * lo;
            hi = (hi >= 0.f) ? hi : 0.1f * hi;
            const int n = tx + 16 * j;
            ob[(size_t)(m0 + 2 * u) * N_ + n]     = lo;
            ob[(size_t)(m0 + 2 * u + 1) * N_ + n] = hi;
        }
    }
}

// ---------------------------------------------------------------------------
// Inputs (metadata order): 0 xy [4,2,16384] f32, 1 feat_2d [4,128,96,160] f32,
// 2 feat_3d [4,128,16384] f32, 3 W [128,256] f32, 4 b [128] f32.
// Output: [4,128,16384] f32.
// ---------------------------------------------------------------------------
extern "C" void kernel_launch(void* const* d_in, const int* in_sizes, int n_in,
                              void* d_out, int out_size) {
    const float* xy   = (const float*)d_in[0];
    const float* f2d  = (const float*)d_in[1];
    const float* f3d  = (const float*)d_in[2];
    const float* Wm   = (const float*)d_in[3];
    const float* bias = (const float*)d_in[4];
    float* out = (float*)d_out;

    k_transpose_f2d<<<dim3(HW / 32, C2D / 32, B_), dim3(32, 8)>>>(f2d);
    k_transpose_w<<<(CI * CO) / 256, 256>>>(Wm);

    const int smem_bytes = (TN * SB_STRIDE + 64 * CO) * (int)sizeof(float); // 99328
    cudaFuncSetAttribute(k_fused, cudaFuncAttributeMaxDynamicSharedMemorySize, smem_bytes);
    k_fused<<<dim3(N_ / TN, B_), 256, smem_bytes>>>(xy, f3d, bias, out);
}